// round 16
// baseline (speedup 1.0000x reference)
#include <cuda_runtime.h>
#include <cuda_fp16.h>
#include <math.h>
#include <stdint.h>

#define B_    2048
#define S_    128
#define D_    1024
#define DFF_  4096
#define NCAND 32
#define NACT  546

#define K1    D_              // 1024: pure fp16
#define BM    128
#define BN    64
#define BK    32
#define NCH   (K1/BK)         // 32
#define GT    256             // 8 warps: 4m x 2n, warp tile 32x32

#define STAGE_BYTES 12288     // A 8KB + B 4KB (2 K-rows packed per 128B smem row)
#define NSTAGE 4
#define SM_TOTAL (NSTAGE*STAGE_BYTES)   // 48KB -> 4 CTAs/SM (192KB)
#define B_SMEM_OFF 8192

#define NBLK_B 2048
#define NBLK_A 512

// ---------------- scratch ----------------
__device__ __half g_A2[(size_t)B_   * K1];   // 4 MB
__device__ __half g_B2t[(size_t)DFF_ * K1];  // 8 MB, [n][k]

// ---------------- helpers ----------------
__device__ __forceinline__ uint32_t smem_u32(const void* p) {
    uint32_t a;
    asm("{ .reg .u64 t; cvta.to.shared.u64 t, %1; cvt.u32.u64 %0, t; }" : "=r"(a) : "l"(p));
    return a;
}
__device__ __forceinline__ void cp_async16(uint32_t s, const void* g) {
    asm volatile("cp.async.cg.shared.global [%0], [%1], 16;" :: "r"(s), "l"(g));
}
#define CP_COMMIT() asm volatile("cp.async.commit_group;" ::: "memory")
template <int N>
__device__ __forceinline__ void cp_wait() {
    asm volatile("cp.async.wait_group %0;" :: "n"(N) : "memory");
}
__device__ __forceinline__ void ldsm_x4(uint32_t* r, uint32_t addr) {
    asm volatile("ldmatrix.sync.aligned.m8n8.x4.shared.b16 {%0,%1,%2,%3}, [%4];"
                 : "=r"(r[0]), "=r"(r[1]), "=r"(r[2]), "=r"(r[3]) : "r"(addr));
}
__device__ __forceinline__ void mma16816(float* d, const uint32_t* a, uint32_t b0, uint32_t b1) {
    asm volatile("mma.sync.aligned.m16n8k16.row.col.f32.f16.f16.f32 "
                 "{%0,%1,%2,%3}, {%4,%5,%6,%7}, {%8,%9}, {%0,%1,%2,%3};"
                 : "+f"(d[0]), "+f"(d[1]), "+f"(d[2]), "+f"(d[3])
                 : "r"(a[0]), "r"(a[1]), "r"(a[2]), "r"(a[3]), "r"(b0), "r"(b1));
}
__device__ __forceinline__ float gelu_exact(float x) {
    return 0.5f * x * (1.0f + erff(x * 0.70710678118654752f));
}
__device__ __forceinline__ uint32_t pack_h2(__half x, __half y) {
    __half2 v; v.x = x; v.y = y;
    return *(uint32_t*)&v;
}
// packed-row smem offset for matrix row m, 16B chunk c2 (row = 64B, 2 rows per 128B line)
__device__ __forceinline__ uint32_t pk_off(int m, int c2) {
    uint32_t srow = (uint32_t)m >> 1;
    uint32_t xb   = (srow & 7) << 4;
    return srow * 128 + (((((uint32_t)m & 1) << 6) | ((uint32_t)c2 << 4)) ^ xb);
}

// ---------------- kernel 1: fused conv (B first, then A) ----------------
__global__ void conv_kernel(const int* __restrict__ cand,
                            const float* __restrict__ encode,
                            const float* __restrict__ W1,
                            const float* __restrict__ b2,
                            float* __restrict__ out) {
    if (blockIdx.x < NBLK_B) {
        __shared__ float tile[32][68];
        const int bb = blockIdx.x;
        const int n0 = (bb & 63) * 64;
        const int k0 = (bb >> 6) * 32;
        {
            const int r  = threadIdx.x >> 4;
            const int c4 = (threadIdx.x & 15) * 4;
            #pragma unroll
            for (int rr = r; rr < 32; rr += 16) {
                float4 v = *(const float4*)&W1[(size_t)(k0 + rr) * DFF_ + n0 + c4];
                *(float4*)&tile[rr][c4] = v;
            }
        }
        __syncthreads();
        {
            const int n  = threadIdx.x & 63;
            const int kq = (threadIdx.x >> 6) * 8;
            uint32_t hi[4];
            #pragma unroll
            for (int i = 0; i < 4; i++) {
                hi[i] = pack_h2(__float2half_rn(tile[kq + 2 * i][n]),
                                __float2half_rn(tile[kq + 2 * i + 1][n]));
            }
            *(uint4*)(g_B2t + (size_t)(n0 + n) * K1 + k0 + kq) = *(uint4*)hi;
        }
    } else {
        const int b0 = (blockIdx.x - NBLK_B) * 4;
        __shared__ int srow[4];
        const int w = threadIdx.x >> 5, lane = threadIdx.x & 31;
        if (w < 4) {
            int c = cand[(b0 + w) * NCAND + lane];
            unsigned m = __ballot_sync(0xffffffffu, c >= NACT);
            if (lane == 0) {
                srow[w] = (S_ - NCAND) + (__ffs(m) - 1);
                out[b0 + w] = b2[0];
            }
        }
        __syncthreads();
        const int i = threadIdx.x;
        #pragma unroll
        for (int r = 0; r < 4; r++) {
            const int b = b0 + r;
            float4 a = ((const float4*)(encode + ((size_t)b * S_ + srow[r]) * D_))[i];
            uint2 hv;
            hv.x = pack_h2(__float2half_rn(a.x), __float2half_rn(a.y));
            hv.y = pack_h2(__float2half_rn(a.z), __float2half_rn(a.w));
            *(uint2*)(g_A2 + (size_t)b * K1 + 4 * i) = hv;
        }
    }
    cudaTriggerProgrammaticLaunchCompletion();
}

// ---------------- kernel 2: fp16 HMMA GEMM, BK=32, 4-stage, 4 CTAs/SM ----------------
__global__ __launch_bounds__(GT, 4)
void gemm_kernel(const float* __restrict__ b1,
                 const float* __restrict__ W2,
                 float* __restrict__ out) {
    extern __shared__ char smem[];
    const uint32_t sb = smem_u32(smem);
    const int tid  = threadIdx.x;
    const int wid  = tid >> 5;
    const int lane = tid & 31;
    const int wm = wid >> 1;     // 0..3 (32 rows each)
    const int wn = wid & 1;      // 0..1 (32 cols each)
    const int bn = blockIdx.x;   // 0..63
    const int bm = blockIdx.y;   // 0..15

    // ---- cp.async mapping: A 2 chunks + B 1 chunk per thread per stage
    const int am  = tid >> 1;            // A matrix row 0..127
    const int acb = (tid & 1) * 2;       // A chunk base 0 or 2
    const char* aPtr = (const char*)(g_A2 + (size_t)(bm * BM + am) * K1) + acb * 16;
    const uint32_t aS0 = pk_off(am, acb);
    const uint32_t aS1 = pk_off(am, acb + 1);
    const int bmr = tid >> 2;            // B matrix row 0..63
    const int bc2 = tid & 3;
    const char* bPtr = (const char*)(g_B2t + (size_t)(bn * BN + bmr) * K1) + bc2 * 16;
    const uint32_t bS = B_SMEM_OFF + pk_off(bmr, bc2);

    // ---- ldmatrix offsets (chunk bits XORed in per ks)
    const int l15 = lane & 15;
    const uint32_t hb = (uint32_t)(lane >> 4) << 4;   // 0 or 16
    uint32_t aoff[2], boff[2];
    #pragma unroll
    for (int mt = 0; mt < 2; mt++)
        aoff[mt] = pk_off(wm * 32 + mt * 16 + l15, 0);
    #pragma unroll
    for (int u = 0; u < 2; u++)
        boff[u] = B_SMEM_OFF + pk_off(wn * 32 + u * 16 + l15, 0);

    float acc[2][4][4];
    #pragma unroll
    for (int i = 0; i < 2; i++)
        #pragma unroll
        for (int j = 0; j < 4; j++)
            #pragma unroll
            for (int r = 0; r < 4; r++) acc[i][j][r] = 0.f;

    cudaGridDependencySynchronize();

    #define LOAD_STAGE(buf, c)                                                  \
        do {                                                                    \
            const uint32_t _s = sb + (buf) * STAGE_BYTES;                       \
            cp_async16(_s + aS0, aPtr + (c) * 64);                              \
            cp_async16(_s + aS1, aPtr + (c) * 64 + 16);                         \
            cp_async16(_s + bS,  bPtr + (c) * 64);                              \
            CP_COMMIT();                                                        \
        } while (0)

    LOAD_STAGE(0, 0);
    LOAD_STAGE(1, 1);
    LOAD_STAGE(2, 2);

    #pragma unroll 4
    for (int c = 0; c < NCH; c++) {
        cp_wait<2>();
        __syncthreads();
        if (c + 3 < NCH) LOAD_STAGE((c + 3) & 3, c + 3);

        const uint32_t stg = sb + (uint32_t)((c & 3) * STAGE_BYTES);

        #pragma unroll
        for (int ks = 0; ks < 2; ks++) {
            const uint32_t cx = ((uint32_t)ks << 5) | hb;
            uint32_t afr[2][4], bfr[2][4];
            ldsm_x4(afr[0], stg + (aoff[0] ^ cx));
            ldsm_x4(afr[1], stg + (aoff[1] ^ cx));
            ldsm_x4(bfr[0], stg + (boff[0] ^ cx));
            ldsm_x4(bfr[1], stg + (boff[1] ^ cx));
            #pragma unroll
            for (int mt = 0; mt < 2; mt++)
                #pragma unroll
                for (int nt = 0; nt < 4; nt++)
                    mma16816(acc[mt][nt], afr[mt],
                             bfr[nt >> 1][nt & 1], bfr[nt >> 1][(nt & 1) + 2]);
        }
    }

    // ---- Epilogue: bias + exact gelu + dot W2, reduce, atomicAdd ----
    const int qn = lane & 3;
    const int qr = lane >> 2;
    float bia[4][2], w2v[4][2];
    #pragma unroll
    for (int nt = 0; nt < 4; nt++) {
        int n = bn * BN + wn * 32 + nt * 8 + qn * 2;
        bia[nt][0] = __ldg(&b1[n]);     bia[nt][1] = __ldg(&b1[n + 1]);
        w2v[nt][0] = __ldg(&W2[n]);     w2v[nt][1] = __ldg(&W2[n + 1]);
    }
    #pragma unroll
    for (int mt = 0; mt < 2; mt++) {
        float p0 = 0.f, p1 = 0.f;
        #pragma unroll
        for (int nt = 0; nt < 4; nt++) {
            const float* d = acc[mt][nt];
            p0 = fmaf(gelu_exact(d[0] + bia[nt][0]), w2v[nt][0], p0);
            p0 = fmaf(gelu_exact(d[1] + bia[nt][1]), w2v[nt][1], p0);
            p1 = fmaf(gelu_exact(d[2] + bia[nt][0]), w2v[nt][0], p1);
            p1 = fmaf(gelu_exact(d[3] + bia[nt][1]), w2v[nt][1], p1);
        }
        p0 += __shfl_xor_sync(0xffffffffu, p0, 1);
        p0 += __shfl_xor_sync(0xffffffffu, p0, 2);
        p1 += __shfl_xor_sync(0xffffffffu, p1, 1);
        p1 += __shfl_xor_sync(0xffffffffu, p1, 2);
        if (qn == 0) {
            int m = bm * BM + wm * 32 + mt * 16 + qr;
            atomicAdd(&out[m], p0);
            atomicAdd(&out[m + 8], p1);
        }
    }
}

// ---------------- launcher ----------------
extern "C" void kernel_launch(void* const* d_in, const int* in_sizes, int n_in,
                              void* d_out, int out_size) {
    const int*   cand   = (const int*)d_in[0];
    const float* encode = (const float*)d_in[1];
    const float* W1     = (const float*)d_in[2];
    const float* b1     = (const float*)d_in[3];
    const float* W2     = (const float*)d_in[4];
    const float* b2     = (const float*)d_in[5];
    float* out = (float*)d_out;

    static int smem_set = 0;
    if (!smem_set) {
        cudaFuncSetAttribute(gemm_kernel, cudaFuncAttributeMaxDynamicSharedMemorySize, SM_TOTAL);
        smem_set = 1;
    }

    conv_kernel<<<NBLK_B + NBLK_A, 256>>>(cand, encode, W1, b2, out);

    cudaLaunchConfig_t cfg = {};
    cfg.gridDim  = dim3(DFF_ / BN, B_ / BM, 1);   // (64, 16)
    cfg.blockDim = dim3(GT, 1, 1);
    cfg.dynamicSmemBytes = SM_TOTAL;
    cfg.stream = 0;
    cudaLaunchAttribute attrs[1];
    attrs[0].id = cudaLaunchAttributeProgrammaticStreamSerialization;
    attrs[0].val.programmaticStreamSerializationAllowed = 1;
    cfg.attrs = attrs;
    cfg.numAttrs = 1;
    cudaLaunchKernelEx(&cfg, gemm_kernel, b1, W2, out);
}

// round 17
// speedup vs baseline: 1.2778x; 1.2778x over previous
#include <cuda_runtime.h>
#include <cuda_fp16.h>
#include <math.h>
#include <stdint.h>

#define B_    2048
#define S_    128
#define D_    1024
#define DFF_  4096
#define NCAND 32
#define NACT  546

#define K1    D_              // 1024: pure fp16
#define BM    128
#define BN    128
#define BK    64
#define NCH   (K1/BK)         // 16
#define GT    512             // 16 warps: 4m x 4n, warp tile 32x32

#define STAGE_BYTES 32768     // A 16KB + B 16KB
#define NSTAGE 3
#define SM_TOTAL (NSTAGE*STAGE_BYTES)   // 96KB -> 2 CTAs/SM (192KB), 32 warps
#define B_OFF 16384

#define NBLK_B 2048
#define NBLK_A 512

// ---------------- scratch ----------------
__device__ __half g_A2[(size_t)B_   * K1];   // 4 MB
__device__ __half g_B2t[(size_t)DFF_ * K1];  // 8 MB, [n][k]

// ---------------- helpers ----------------
__device__ __forceinline__ uint32_t smem_u32(const void* p) {
    uint32_t a;
    asm("{ .reg .u64 t; cvta.to.shared.u64 t, %1; cvt.u32.u64 %0, t; }" : "=r"(a) : "l"(p));
    return a;
}
__device__ __forceinline__ void cp_async16(uint32_t s, const void* g) {
    asm volatile("cp.async.cg.shared.global [%0], [%1], 16;" :: "r"(s), "l"(g));
}
#define CP_COMMIT() asm volatile("cp.async.commit_group;" ::: "memory")
template <int N>
__device__ __forceinline__ void cp_wait() {
    asm volatile("cp.async.wait_group %0;" :: "n"(N) : "memory");
}
__device__ __forceinline__ void ldsm_x4(uint32_t* r, uint32_t addr) {
    asm volatile("ldmatrix.sync.aligned.m8n8.x4.shared.b16 {%0,%1,%2,%3}, [%4];"
                 : "=r"(r[0]), "=r"(r[1]), "=r"(r[2]), "=r"(r[3]) : "r"(addr));
}
__device__ __forceinline__ void mma16816(float* d, const uint32_t* a, uint32_t b0, uint32_t b1) {
    asm volatile("mma.sync.aligned.m16n8k16.row.col.f32.f16.f16.f32 "
                 "{%0,%1,%2,%3}, {%4,%5,%6,%7}, {%8,%9}, {%0,%1,%2,%3};"
                 : "+f"(d[0]), "+f"(d[1]), "+f"(d[2]), "+f"(d[3])
                 : "r"(a[0]), "r"(a[1]), "r"(a[2]), "r"(a[3]), "r"(b0), "r"(b1));
}
__device__ __forceinline__ float gelu_exact(float x) {
    return 0.5f * x * (1.0f + erff(x * 0.70710678118654752f));
}
__device__ __forceinline__ uint32_t swz(int r, int c2) {
    return (uint32_t)(r * 128 + ((c2 * 16) ^ ((r & 7) * 16)));
}
__device__ __forceinline__ uint32_t pack_h2(__half x, __half y) {
    __half2 v; v.x = x; v.y = y;
    return *(uint32_t*)&v;
}

// ---------------- kernel 1: fused conv (B first, then A) ----------------
__global__ void conv_kernel(const int* __restrict__ cand,
                            const float* __restrict__ encode,
                            const float* __restrict__ W1,
                            const float* __restrict__ b2,
                            float* __restrict__ out) {
    if (blockIdx.x < NBLK_B) {
        __shared__ float tile[32][68];
        const int bb = blockIdx.x;
        const int n0 = (bb & 63) * 64;
        const int k0 = (bb >> 6) * 32;
        {
            const int r  = threadIdx.x >> 4;
            const int c4 = (threadIdx.x & 15) * 4;
            #pragma unroll
            for (int rr = r; rr < 32; rr += 16) {
                float4 v = *(const float4*)&W1[(size_t)(k0 + rr) * DFF_ + n0 + c4];
                *(float4*)&tile[rr][c4] = v;
            }
        }
        __syncthreads();
        {
            const int n  = threadIdx.x & 63;
            const int kq = (threadIdx.x >> 6) * 8;
            uint32_t hi[4];
            #pragma unroll
            for (int i = 0; i < 4; i++) {
                hi[i] = pack_h2(__float2half_rn(tile[kq + 2 * i][n]),
                                __float2half_rn(tile[kq + 2 * i + 1][n]));
            }
            *(uint4*)(g_B2t + (size_t)(n0 + n) * K1 + k0 + kq) = *(uint4*)hi;
        }
    } else {
        const int b0 = (blockIdx.x - NBLK_B) * 4;
        __shared__ int srow[4];
        const int w = threadIdx.x >> 5, lane = threadIdx.x & 31;
        if (w < 4) {
            int c = cand[(b0 + w) * NCAND + lane];
            unsigned m = __ballot_sync(0xffffffffu, c >= NACT);
            if (lane == 0) {
                srow[w] = (S_ - NCAND) + (__ffs(m) - 1);
                out[b0 + w] = b2[0];
            }
        }
        __syncthreads();
        const int i = threadIdx.x;
        #pragma unroll
        for (int r = 0; r < 4; r++) {
            const int b = b0 + r;
            float4 a = ((const float4*)(encode + ((size_t)b * S_ + srow[r]) * D_))[i];
            uint2 hv;
            hv.x = pack_h2(__float2half_rn(a.x), __float2half_rn(a.y));
            hv.y = pack_h2(__float2half_rn(a.z), __float2half_rn(a.w));
            *(uint2*)(g_A2 + (size_t)b * K1 + 4 * i) = hv;
        }
    }
    cudaTriggerProgrammaticLaunchCompletion();
}

// ---------------- kernel 2: fp16 HMMA GEMM, 128x128 tile, 16 warps, 3-stage ----------------
__global__ __launch_bounds__(GT, 2)
void gemm_kernel(const float* __restrict__ b1,
                 const float* __restrict__ W2,
                 float* __restrict__ out) {
    extern __shared__ char smem[];
    const uint32_t sb = smem_u32(smem);
    const int tid  = threadIdx.x;
    const int wid  = tid >> 5;
    const int lane = tid & 31;
    const int wm = wid >> 2;     // 0..3 (32 rows each)
    const int wn = wid & 3;      // 0..3 (32 cols each)
    const int bn = blockIdx.x;   // 0..31
    const int bm = blockIdx.y;   // 0..15

    // ---- cp.async mapping: 512 threads; A 2 chunks + B 2 chunks per thread
    const int lr  = tid >> 3;    // row 0..63
    const int lc2 = tid & 7;     // 16B chunk in row
    const char* aPtr = (const char*)(g_A2  + (size_t)(bm * BM + lr) * K1 + lc2 * 8);
    const char* bPtr = (const char*)(g_B2t + (size_t)(bn * BN + lr) * K1 + lc2 * 8);
    const uint32_t sw0 = swz(lr, lc2);           // rows lr and lr+64 share (r&7): +8192
    #define R64 ((size_t)64 * K1 * 2)

    // ---- ldmatrix address constants (swizzle algebra hoist)
    const int l15 = lane & 15;
    const uint32_t xb  = (uint32_t)(l15 & 7) * 16;
    const uint32_t hlx = ((uint32_t)(lane >> 4) * 16) ^ (xb & 16);
    const uint32_t xh  = xb & 0x60;
    const uint32_t aBase = sb + (uint32_t)(wm * 32 + l15) * 128 + hlx;
    const uint32_t bBase = sb + (uint32_t)(wn * 32 + l15) * 128 + hlx + B_OFF;
    const uint32_t xh0 = 0 ^ xh, xh1 = 32 ^ xh, xh2 = 64 ^ xh, xh3 = 96 ^ xh;

    float acc[2][4][4];
    #pragma unroll
    for (int i = 0; i < 2; i++)
        #pragma unroll
        for (int j = 0; j < 4; j++)
            #pragma unroll
            for (int r = 0; r < 4; r++) acc[i][j][r] = 0.f;

    cudaGridDependencySynchronize();

    #define LOAD_STAGE(buf, c)                                                  \
        do {                                                                    \
            const uint32_t _s = sb + (buf) * STAGE_BYTES;                       \
            cp_async16(_s + sw0,                aPtr + (c) * 128);              \
            cp_async16(_s + sw0 + 8192,         aPtr + R64 + (c) * 128);        \
            cp_async16(_s + sw0 + B_OFF,        bPtr + (c) * 128);              \
            cp_async16(_s + sw0 + B_OFF + 8192, bPtr + R64 + (c) * 128);        \
            CP_COMMIT();                                                        \
        } while (0)

    LOAD_STAGE(0, 0);
    LOAD_STAGE(1, 1);

    #pragma unroll
    for (int c = 0; c < NCH; c++) {
        cp_wait<1>();
        __syncthreads();
        if (c + 2 < NCH) LOAD_STAGE((c + 2) % NSTAGE, c + 2);

        const uint32_t stg = (uint32_t)((c % NSTAGE) * STAGE_BYTES);
        const uint32_t ksofs[4] = {stg + xh0, stg + xh1, stg + xh2, stg + xh3};

        #pragma unroll
        for (int ks = 0; ks < 4; ks++) {
            uint32_t afr[2][4], bfr[2][4];
            #pragma unroll
            for (int mt = 0; mt < 2; mt++) ldsm_x4(afr[mt], aBase + ksofs[ks] + mt * 2048);
            #pragma unroll
            for (int u = 0; u < 2; u++)    ldsm_x4(bfr[u],  bBase + ksofs[ks] + u * 2048);
            #pragma unroll
            for (int mt = 0; mt < 2; mt++)
                #pragma unroll
                for (int nt = 0; nt < 4; nt++)
                    mma16816(acc[mt][nt], afr[mt],
                             bfr[nt >> 1][nt & 1], bfr[nt >> 1][(nt & 1) + 2]);
        }
    }

    // ---- Epilogue: bias + exact gelu + dot W2, reduce, atomicAdd ----
    const int qn = lane & 3;
    const int qr = lane >> 2;
    float bia[4][2], w2v[4][2];
    #pragma unroll
    for (int nt = 0; nt < 4; nt++) {
        int n = bn * BN + wn * 32 + nt * 8 + qn * 2;
        bia[nt][0] = __ldg(&b1[n]);     bia[nt][1] = __ldg(&b1[n + 1]);
        w2v[nt][0] = __ldg(&W2[n]);     w2v[nt][1] = __ldg(&W2[n + 1]);
    }
    #pragma unroll
    for (int mt = 0; mt < 2; mt++) {
        float p0 = 0.f, p1 = 0.f;
        #pragma unroll
        for (int nt = 0; nt < 4; nt++) {
            const float* d = acc[mt][nt];
            p0 = fmaf(gelu_exact(d[0] + bia[nt][0]), w2v[nt][0], p0);
            p0 = fmaf(gelu_exact(d[1] + bia[nt][1]), w2v[nt][1], p0);
            p1 = fmaf(gelu_exact(d[2] + bia[nt][0]), w2v[nt][0], p1);
            p1 = fmaf(gelu_exact(d[3] + bia[nt][1]), w2v[nt][1], p1);
        }
        p0 += __shfl_xor_sync(0xffffffffu, p0, 1);
        p0 += __shfl_xor_sync(0xffffffffu, p0, 2);
        p1 += __shfl_xor_sync(0xffffffffu, p1, 1);
        p1 += __shfl_xor_sync(0xffffffffu, p1, 2);
        if (qn == 0) {
            int m = bm * BM + wm * 32 + mt * 16 + qr;
            atomicAdd(&out[m], p0);
            atomicAdd(&out[m + 8], p1);
        }
    }
}

// ---------------- launcher ----------------
extern "C" void kernel_launch(void* const* d_in, const int* in_sizes, int n_in,
                              void* d_out, int out_size) {
    const int*   cand   = (const int*)d_in[0];
    const float* encode = (const float*)d_in[1];
    const float* W1     = (const float*)d_in[2];
    const float* b1     = (const float*)d_in[3];
    const float* W2     = (const float*)d_in[4];
    const float* b2     = (const float*)d_in[5];
    float* out = (float*)d_out;

    static int smem_set = 0;
    if (!smem_set) {
        cudaFuncSetAttribute(gemm_kernel, cudaFuncAttributeMaxDynamicSharedMemorySize, SM_TOTAL);
        smem_set = 1;
    }

    conv_kernel<<<NBLK_B + NBLK_A, 256>>>(cand, encode, W1, b2, out);

    cudaLaunchConfig_t cfg = {};
    cfg.gridDim  = dim3(DFF_ / BN, B_ / BM, 1);   // (32, 16)
    cfg.blockDim = dim3(GT, 1, 1);
    cfg.dynamicSmemBytes = SM_TOTAL;
    cfg.stream = 0;
    cudaLaunchAttribute attrs[1];
    attrs[0].id = cudaLaunchAttributeProgrammaticStreamSerialization;
    attrs[0].val.programmaticStreamSerializationAllowed = 1;
    cfg.attrs = attrs;
    cfg.numAttrs = 1;
    cudaLaunchKernelEx(&cfg, gemm_kernel, b1, W2, out);
}